// round 5
// baseline (speedup 1.0000x reference)
#include <cuda_runtime.h>

#define L_FIXED 2048
#define TILE    128
#define NT      (L_FIXED / TILE)          // 16
#define NTP     (NT * (NT + 1) / 2)       // 136
#define MAXB    16
#define EPSF    1e-8f
#define THRC    2.2601f                   // 1.5^2 + margin for fp32 dot-form error
#define NTHREADS 256

typedef unsigned long long ull;

// ---- global accumulators (zero-initialized at load, reset by finalize) ----
__device__ double   g_clash = 0.0;
__device__ double   g_bn    = 0.0;
__device__ double   g_bd    = 0.0;
__device__ double   g_lin   = 0.0;
__device__ double   g_S[MAXB];
__device__ unsigned g_count = 0;

// ---- helpers ----
__device__ __forceinline__ ull pack2(float x) {
    ull r; asm("mov.b64 %0, {%1, %1};" : "=l"(r) : "f"(x)); return r;
}
__device__ __forceinline__ ull fma2(ull a, ull b, ull c) {
    ull r; asm("fma.rn.f32x2 %0, %1, %2, %3;" : "=l"(r) : "l"(a), "l"(b), "l"(c)); return r;
}
__device__ __forceinline__ void unpack2(ull v, float &lo, float &hi) {
    asm("mov.b64 {%0, %1}, %2;" : "=f"(lo), "=f"(hi) : "l"(v));
}
__device__ __forceinline__ float sqrt_apx(float x) {
    float r; asm("sqrt.approx.f32 %0, %1;" : "=f"(r) : "f"(x)); return r;
}
__device__ __forceinline__ float warp_sum(float v) {
    #pragma unroll
    for (int off = 16; off > 0; off >>= 1)
        v += __shfl_down_sync(0xffffffffu, v, off);
    return v;
}
// bounded lattice displacement for masked atoms: min separation 16,
// coords <= 1.25e4 so fp32 dot-form error (~35) << 16^2
__device__ __forceinline__ void displace(int i, float &X, float &Y, float &Z) {
    X = 1.0e4f + 16.0f * (float)(i & 127);
    Y = 16.0f * (float)(i >> 7);
    Z = 0.0f;
}

// ============================================================
// Single fused kernel. grid = (NTP, B), block = 256.
// Unified tile loop (dot-product form, per-row threshold, vote-gated
// slow path doing sqrt + seq-sep + mask). Diagonal blocks add bond/stat
// terms; last block finalizes.
// ============================================================
__global__ void __launch_bounds__(NTHREADS)
fused_violation_kernel(const float* __restrict__ pos,
                       const float* __restrict__ mask,
                       float* __restrict__ out, int B)
{
    const int p   = blockIdx.x;
    const int b   = blockIdx.y;
    const int tid = threadIdx.x;

    // closed-form triangular decode: cum(ti) = ti*(33-ti)/2
    const int ti  = (int)((33.0f - sqrtf(1089.0f - 8.0f * (float)p)) * 0.5f);
    const int tj  = ti + (p - (ti * (33 - ti)) / 2);
    const int i0  = ti * TILE, j0 = tj * TILE;

    const float* P = pos  + (size_t)b * L_FIXED * 3;
    const float* M = mask + (size_t)b * L_FIXED;

    // ---- stage j tile: x, y, z, q = |r|^2, mask (packed pairs) ----
    __shared__ ull sjx[TILE/2], sjy[TILE/2], sjz[TILE/2], sjq[TILE/2], sjm[TILE/2];
    if (tid < TILE) {
        int j = j0 + tid;
        float mj = M[j];
        float X = P[3*j], Y = P[3*j+1], Z = P[3*j+2];
        if (mj == 0.0f) displace(j, X, Y, Z);
        ((float*)sjx)[tid] = X;
        ((float*)sjy)[tid] = Y;
        ((float*)sjz)[tid] = Z;
        ((float*)sjq)[tid] = X*X + Y*Y + Z*Z;
        ((float*)sjm)[tid] = mj;
    }

    // ---- per-thread i rows (4 consecutive): -2*coords packed, q, thr, mask ----
    const int q  = tid & 31;          // i quad (lane)
    const int s  = tid >> 5;          // j slice (warp-uniform)
    const int ibase = i0 + 4 * q;
    ull  x2[4], y2[4], z2[4];
    float qi[4], thr[4], mi[4];
    {
        const float4* P4 = (const float4*)(P + 3 * ibase);
        float4 v0 = P4[0], v1 = P4[1], v2 = P4[2];
        float c[12] = {v0.x, v0.y, v0.z, v0.w, v1.x, v1.y, v1.z, v1.w,
                       v2.x, v2.y, v2.z, v2.w};
        #pragma unroll
        for (int r = 0; r < 4; r++) {
            int i = ibase + r;
            float m = M[i];
            float X = c[3*r], Y = c[3*r+1], Z = c[3*r+2];
            if (m == 0.0f) displace(i, X, Y, Z);
            float qq = X*X + Y*Y + Z*Z;
            qi[r]  = qq;
            thr[r] = THRC - qq;
            mi[r]  = m;
            x2[r] = pack2(-2.0f * X);
            y2[r] = pack2(-2.0f * Y);
            z2[r] = pack2(-2.0f * Z);
        }
    }
    __syncthreads();

    float acc = 0.0f;
    const int k0 = s * 8;

    #pragma unroll
    for (int k = k0; k < k0 + 8; k++) {
        ull xj = sjx[k], yj = sjy[k], zj = sjz[k], qj = sjq[k];
        float ulo[4], uhi[4];
        #pragma unroll
        for (int r = 0; r < 4; r++) {
            ull u = fma2(x2[r], xj, fma2(y2[r], yj, fma2(z2[r], zj, qj)));
            unpack2(u, ulo[r], uhi[r]);
        }
        float g0 = thr[0] - fminf(ulo[0], uhi[0]);
        float g1 = thr[1] - fminf(ulo[1], uhi[1]);
        float g2 = thr[2] - fminf(ulo[2], uhi[2]);
        float g3 = thr[3] - fminf(ulo[3], uhi[3]);
        float g  = fmaxf(fmaxf(g0, g1), fmaxf(g2, g3));
        if (__any_sync(0xffffffffu, g > 0.0f)) {
            float ml, mh; unpack2(sjm[k], ml, mh);
            int jlo = j0 + 2 * k;
            #pragma unroll
            for (int r = 0; r < 4; r++) {
                int i = ibase + r;
                float vl = fmaxf(1.5f - sqrt_apx(ulo[r] + qi[r] + EPSF), 0.0f);
                float vh = fmaxf(1.5f - sqrt_apx(uhi[r] + qi[r] + EPSF), 0.0f);
                if (jlo - i     <= 2) vl = 0.0f;   // seq-sep (also kills j<=i)
                if (jlo + 1 - i <= 2) vh = 0.0f;
                acc += mi[r] * (vl * ml + vh * mh);
            }
        }
    }

    // ---- block reduction of clash partial ----
    __shared__ float swr[NTHREADS / 32];
    acc = warp_sum(acc);
    if ((tid & 31) == 0) swr[tid >> 5] = acc;
    __syncthreads();
    if (tid == 0) {
        float t = 0.0f;
        #pragma unroll
        for (int w = 0; w < NTHREADS / 32; w++) t += swr[w];
        atomicAdd(&g_clash, (double)t);
    }

    // ---- diagonal blocks: bond term + mask statistics ----
    if (ti == tj) {
        float bn = 0.0f, bd = 0.0f, S = 0.0f, lin = 0.0f;
        if (tid < TILE) {
            int i = i0 + tid;
            float m = M[i];
            S = m; lin = m * m;
            if (i + 1 < L_FIXED) {
                float mj = M[i + 1];
                float dx = P[3*(i+1)]   - P[3*i];
                float dy = P[3*(i+1)+1] - P[3*i+1];
                float dz = P[3*(i+1)+2] - P[3*i+2];
                float d  = sqrtf(dx*dx + dy*dy + dz*dz + EPSF);
                float viol = fmaxf(fabsf(d - 3.8f) - 0.4f, 0.0f);
                bd = m * mj;
                bn = viol * bd;
                lin += 2.0f * bd;
            }
            if (i + 2 < L_FIXED) lin += 2.0f * m * M[i + 2];
        }
        bn  = warp_sum(bn);
        bd  = warp_sum(bd);
        S   = warp_sum(S);
        lin = warp_sum(lin);
        __shared__ float sst[NTHREADS / 32][4];
        if ((tid & 31) == 0) {
            int w = tid >> 5;
            sst[w][0] = bn; sst[w][1] = bd; sst[w][2] = S; sst[w][3] = lin;
        }
        __syncthreads();
        if (tid == 0) {
            double tbn = 0, tbd = 0, tS = 0, tlin = 0;
            #pragma unroll
            for (int w = 0; w < NTHREADS / 32; w++) {
                tbn += sst[w][0]; tbd += sst[w][1];
                tS  += sst[w][2]; tlin += sst[w][3];
            }
            atomicAdd(&g_bn,  tbn);
            atomicAdd(&g_bd,  tbd);
            atomicAdd(&g_S[b], tS);
            atomicAdd(&g_lin, tlin);
        }
    }

    // ---- last-block finalize ----
    __threadfence();
    __shared__ bool is_last;
    if (tid == 0) {
        unsigned total = gridDim.x * gridDim.y;
        is_last = (atomicAdd(&g_count, 1u) == total - 1u);
    }
    __syncthreads();
    if (is_last && tid == 0) {
        double pd = 0.0;
        #pragma unroll
        for (int bb = 0; bb < MAXB; bb++) {
            if (bb < B) {
                double Sb = *((volatile double*)&g_S[bb]);
                pd += Sb * Sb;
            }
        }
        pd -= *((volatile double*)&g_lin);
        double bn = *((volatile double*)&g_bn);
        double bd = *((volatile double*)&g_bd);
        double cl = *((volatile double*)&g_clash);
        double bond  = bn / (bd + 1e-8);
        double clash = 2.0 * cl / (pd + 1e-8);
        out[0] = (float)bond;
        out[1] = (float)clash;
        out[2] = (float)(bond + clash);
        g_clash = 0.0; g_bn = 0.0; g_bd = 0.0; g_lin = 0.0; g_count = 0u;
        #pragma unroll
        for (int bb = 0; bb < MAXB; bb++) g_S[bb] = 0.0;
    }
}

extern "C" void kernel_launch(void* const* d_in, const int* in_sizes, int n_in,
                              void* d_out, int out_size)
{
    const float* pos  = (const float*)d_in[0];
    const float* mask = (const float*)d_in[1];
    int B = in_sizes[1] / L_FIXED;
    if (B > MAXB) B = MAXB;

    dim3 grid(NTP, B);
    fused_violation_kernel<<<grid, NTHREADS>>>(pos, mask, (float*)d_out, B);
}